// round 13
// baseline (speedup 1.0000x reference)
#include <cuda_runtime.h>
#include <cuda_fp16.h>
#include <math.h>

#define D  48
#define D2 (48*48)
#define D3 (48*48*48)
#define TS 216     // fp32 token-row stride: 6 quads * 36 floats (bank-padded)
#define VTS 200    // fp16 v token-row stride in halves (24pd*8c=192 + 8 pad)

// padded pd offset: quad stride 36 (not 32) -> conflict-free c-transposes
#define PDOFF(pd) ((((pd) >> 2) * 36) + (((pd) & 3) * 8))

#define STG_STRIDE 52
#define STG_ROWS   8

// ---------------------------------------------------------------------------
// attention core: warp-per-window; q/k fp32 in sP, v fp16 in sV.
// ---------------------------------------------------------------------------
__device__ __forceinline__ void attn_core(
    float* __restrict__ sP, const __half* __restrict__ sV,
    const float* __restrict__ sTabH, int NwLoc, int tid)
{
    const int warp = tid >> 5, lane = tid & 31;
    const float inv_scale = 0.3535533905932738f;
    const int mh = lane / 9, mw = (lane / 3) % 3, md = lane % 3;
    const int tq = mh * 3 + mw;
    const int mbase = mh * 25 + mw * 5 + md + 62;

    for (int wd = warp; wd < NwLoc; wd += 8) {
        if (lane < 27) {
            const int wd3 = wd * 3;
            const int offs[3] = { PDOFF(wd3), PDOFF(wd3 + 1), PDOFF(wd3 + 2) };
            const int offm = offs[md];

            float* qp = sP + tq * TS + offm;
            const float4 q0 = *(const float4*)qp;
            const float4 q1 = *(const float4*)(qp + 4);

            float s[27];
            #pragma unroll
            for (int n = 0; n < 27; n++) {
                const int tn = n / 3, nd = n % 3;
                const float* kp = sP + (9 + tn) * TS + offs[nd];
                const float4 k0 = *(const float4*)kp;
                const float4 k1 = *(const float4*)(kp + 4);
                s[n] = (q0.x * k0.x + q0.y * k0.y + q0.z * k0.z + q0.w * k0.w
                      + q1.x * k1.x + q1.y * k1.y + q1.z * k1.z + q1.w * k1.w)
                       * inv_scale;
            }
            // no-max softmax: |s| bounded (~45) -> exp safe in fp32
            float sum = 0.f;
            #pragma unroll
            for (int n = 0; n < 27; n++) { s[n] = __expf(s[n]); sum += s[n]; }
            const float inv = 1.0f / sum;
            #pragma unroll
            for (int n = 0; n < 27; n++) {
                const int nh = n / 9, nw = (n / 3) % 3, nd = n % 3;
                s[n] = s[n] * inv + sTabH[mbase - (nh * 25 + nw * 5 + nd)];
            }
            float4 a0 = make_float4(0.f, 0.f, 0.f, 0.f);
            float4 a1 = make_float4(0.f, 0.f, 0.f, 0.f);
            #pragma unroll
            for (int n = 0; n < 27; n++) {
                const int tn = n / 3, nd = n % 3;
                const uint4 hv = *(const uint4*)(sV + tn * VTS + (wd3 + nd) * 8);
                const float2 f0 = __half22float2(*(const __half2*)&hv.x);
                const float2 f1 = __half22float2(*(const __half2*)&hv.y);
                const float2 f2 = __half22float2(*(const __half2*)&hv.z);
                const float2 f3 = __half22float2(*(const __half2*)&hv.w);
                const float sn = s[n];
                a0.x += sn * f0.x; a0.y += sn * f0.y;
                a0.z += sn * f1.x; a0.w += sn * f1.y;
                a1.x += sn * f2.x; a1.y += sn * f2.y;
                a1.z += sn * f3.x; a1.w += sn * f3.y;
            }
            *(float4*)qp       = a0;
            *(float4*)(qp + 4) = a1;
        }
    }
}

// ---------------------------------------------------------------------------
// upsample (br>=1): lane-quarter compute into staging carved from the dead
// k region (+ spare rows), then coalesced float4 copy-out.
// ---------------------------------------------------------------------------
template<int BR, int NWLOC>
__device__ __forceinline__ void upsample_staged(
    float* __restrict__ sP, const int* __restrict__ sI0,
    const float* __restrict__ sF, float* __restrict__ out,
    int chbase, int h0, int w0, int dhalf, int tid)
{
    constexpr int BW   = 3 << BR;
    constexpr int LEN  = NWLOC * BW;      // d extent: 48,48,24
    constexpr int QLEN = LEN / 4;         // per-lane quarter
    constexpr int ROWS = 8 * BW * BW;
    constexpr int RPW  = ROWS / 8;        // rows per warp
    const int warp = tid >> 5, lane = tid & 31;
    float* stg = sP + 9 * TS + warp * STG_ROWS * STG_STRIDE;  // dead k region+
    const int dbase = dhalf * LEN;
    const size_t chD3 = (size_t)chbase * D3;
    const int rw0 = warp * RPW;

    for (int rb = 0; rb < RPW; rb += STG_ROWS) {
        const int nr = (RPW - rb < STG_ROWS) ? (RPW - rb) : STG_ROWS;

        // ---- compute: lane = (row, quarter) ----
        const int lrow = lane >> 2, quarter = lane & 3;
        if (lrow < nr) {
            const int r   = rw0 + rb + lrow;
            const int c   = r / (BW * BW);
            const int rem = r - c * (BW * BW);
            const int lh  = rem / BW;
            const int lw  = rem - lh * BW;

            const int   ih0 = sI0[lh], iw0 = sI0[lw];
            const int   ih1 = (ih0 < 2) ? ih0 + 1 : 2;
            const int   iw1 = (iw0 < 2) ? iw0 + 1 : 2;
            const float fh  = sF[lh],  fw  = sF[lw];

            const int o00 = (ih0 * 3 + iw0) * TS + c;
            const int o01 = (ih0 * 3 + iw1) * TS + c;
            const int o10 = (ih1 * 3 + iw0) * TS + c;
            const int o11 = (ih1 * 3 + iw1) * TS + c;

            float* srow = stg + lrow * STG_STRIDE + quarter * QLEN;

            if (BR < 3) {
                constexpr int WPQ = QLEN / BW;        // 2 (br1), 1 (br2)
                const int wdb = quarter * WPQ;
                #pragma unroll
                for (int wi = 0; wi < WPQ; wi++) {
                    const int wd3 = (wdb + wi) * 3;
                    const int pos3[3] = { PDOFF(wd3), PDOFF(wd3 + 1), PDOFF(wd3 + 2) };
                    float T[3];
                    #pragma unroll
                    for (int id = 0; id < 3; id++) {
                        const int po = pos3[id];
                        const float t00 = sP[o00 + po], t01 = sP[o01 + po];
                        const float t10 = sP[o10 + po], t11 = sP[o11 + po];
                        const float a0 = t00 + fw * (t01 - t00);
                        const float a1 = t10 + fw * (t11 - t10);
                        T[id] = a0 + fh * (a1 - a0);
                    }
                    #pragma unroll
                    for (int ld = 0; ld < BW; ld += 2) {
                        float pr[2];
                        #pragma unroll
                        for (int j = 0; j < 2; j++) {
                            const float pos = (float)(ld + j) * (2.0f / (float)(BW - 1));
                            const int   id0 = (pos >= 2.0f) ? 2 : (int)pos;
                            const float fd  = pos - (float)id0;
                            const float lo = T[id0];
                            const float hi = T[(id0 < 2) ? id0 + 1 : 2];
                            pr[j] = lo + fd * (hi - lo);
                        }
                        *(float2*)(srow + wi * BW + ld) = make_float2(pr[0], pr[1]);
                    }
                }
            } else {                                   // BR==3: QLEN=6 of one window
                float T[3];
                #pragma unroll
                for (int id = 0; id < 3; id++) {
                    const int po = id * 8;             // PDOFF(0..2) = 0,8,16
                    const float t00 = sP[o00 + po], t01 = sP[o01 + po];
                    const float t10 = sP[o10 + po], t11 = sP[o11 + po];
                    const float a0 = t00 + fw * (t01 - t00);
                    const float a1 = t10 + fw * (t11 - t10);
                    T[id] = a0 + fh * (a1 - a0);
                }
                const int ldb = quarter * 6;
                #pragma unroll
                for (int j = 0; j < 6; j += 2) {
                    float pr[2];
                    #pragma unroll
                    for (int jj = 0; jj < 2; jj++) {
                        const float pos = (float)(ldb + j + jj) * (2.0f / 23.0f);
                        const int   id0 = (pos >= 2.0f) ? 2 : (int)pos;
                        const float fd  = pos - (float)id0;
                        const float lo = T[id0];
                        const float hi = T[(id0 < 2) ? id0 + 1 : 2];
                        pr[jj] = lo + fd * (hi - lo);
                    }
                    *(float2*)(srow + j) = make_float2(pr[0], pr[1]);
                }
            }
        }
        __syncwarp();

        // ---- copy: coalesced float4 out ----
        const int nq = nr * (LEN / 4);
        for (int i = lane; i < nq; i += 32) {
            const int row    = (i * 4) / LEN;
            const int within = (i * 4) - row * LEN;
            float4 v = *(const float4*)(stg + row * STG_STRIDE + within);
            const int r   = rw0 + rb + row;
            const int c   = r / (BW * BW);
            const int rem = r - c * (BW * BW);
            const int lh  = rem / BW;
            const int lw  = rem - lh * BW;
            *(float4*)(out + chD3 + (size_t)c * D3
                       + (h0 + lh) * D2 + (w0 + lw) * D + dbase + within) = v;
        }
        __syncwarp();
    }
}

// ---------------------------------------------------------------------------
// fusedK: pool-in-CTA + attention + upsample, all branches, one launch.
// grid 4800: [0,64) br3 d-split | [64,192) br2 | [192,704) br1 | [704,4800) br0
// ---------------------------------------------------------------------------
__global__ __launch_bounds__(256, 4) void fusedK(
    const float* __restrict__ Q, const float* __restrict__ Kt,
    const float* __restrict__ V, const float* __restrict__ tab,
    float* __restrict__ out)
{
    __shared__ float  sP[27 * TS];         // q(0-8), k(9-17), staging(9-26)
    __shared__ __half sV[27 * VTS];        // v fp16, c-innermost
    __shared__ float  sTabH[125];
    __shared__ int    sI0[24];
    __shared__ float  sF[24];

    const int cid = blockIdx.x;
    const int tid = threadIdx.x;

    int br, bh, line, dhalf;
    if (cid < 64) {
        br = 3; bh = cid >> 3;
        const int s = cid & 7;
        line = s >> 1; dhalf = s & 1;
    } else if (cid < 192) {
        br = 2; const int s = cid - 64;
        bh = s >> 4; line = s & 15; dhalf = 0;
    } else if (cid < 704) {
        br = 1; const int s = cid - 192;
        bh = s >> 6; line = s & 63; dhalf = 0;
    } else {
        br = 0; const int s = cid - 704;
        bh = s >> 9;
        const int rest = s & 511;
        line = rest >> 1; dhalf = rest & 1;
    }

    const int Nw = 16 >> br;
    const int bw = 3 << br;
    const int wh = line / Nw, ww = line - wh * Nw;
    const int b = bh >> 1, head = bh & 1;
    const int chbase = b * 64 + br * 16 + head * 8;
    const int h0 = wh * bw, w0 = ww * bw;

    if (tid < 125) sTabH[tid] = __ldg(tab + tid * 2 + head);
    if (tid >= 128 && tid - 128 < bw) {
        const int u = tid - 128;
        const float pos = (float)u * (2.0f / (float)(bw - 1));
        int i0 = (int)pos;
        if (i0 > 2) i0 = 2;
        sI0[u] = i0;
        sF[u]  = pos - (float)i0;
    }

    // ---- pool raw input: q/k fp32 -> sP, v fp16 -> sV ----
    if (br == 0) {
        const int dbase = dhalf * 24;
        for (int e = tid; e < 1296; e += 256) {           // 3t*9tok*6q*8c
            const int c    = e & 7;
            const int r    = e >> 3;
            const int pdq  = r % 6;
            const int r2   = r / 6;
            const int token = r2 % 9;
            const int t     = r2 / 9;
            const float* base = (t == 0 ? Q : (t == 1 ? Kt : V))
                + (size_t)(chbase + c) * D3
                + (h0 + token / 3) * D2 + (w0 + token % 3) * D + dbase + 4 * pdq;
            float4 v = __ldg((const float4*)base);
            if (t < 2) {
                float* dst = sP + (t * 9 + token) * TS + pdq * 36 + c;
                dst[0] = v.x; dst[8] = v.y; dst[16] = v.z; dst[24] = v.w;
            } else {
                __half* dst = sV + token * VTS + pdq * 32 + c;
                dst[0]  = __float2half(v.x);
                dst[8]  = __float2half(v.y);
                dst[16] = __float2half(v.z);
                dst[24] = __float2half(v.w);
            }
        }
    } else if (br == 1) {                 // sw=2, pdl-innermost lanes (coalesced)
        for (int e = tid; e < 5184; e += 256) {
            const int pdl  = e % 24;
            const int r    = e / 24;
            const int token = r % 9;
            const int tc    = r / 9;
            const int c     = tc & 7;
            const int t     = tc >> 3;
            const float* base = (t == 0 ? Q : (t == 1 ? Kt : V))
                + (size_t)(chbase + c) * D3;
            const int hh  = h0 + (token / 3) * 2;
            const int wwp = w0 + (token % 3) * 2;
            const float* p = base + hh * D2 + wwp * D + pdl * 2;
            float mx = -1e30f;
            #pragma unroll
            for (int dh = 0; dh < 2; dh++)
                #pragma unroll
                for (int dw = 0; dw < 2; dw++) {
                    float2 a = __ldg((const float2*)(p + dh * D2 + dw * D));
                    mx = fmaxf(mx, fmaxf(a.x, a.y));
                }
            if (t < 2) sP[(t * 9 + token) * TS + PDOFF(pdl) + c] = mx;
            else       sV[token * VTS + pdl * 8 + c] = __float2half(mx);
        }
    } else if (br == 2) {                 // sw=4, pdl-innermost lanes (coalesced)
        for (int e = tid; e < 2592; e += 256) {
            const int pdl  = e % 12;
            const int r    = e / 12;
            const int token = r % 9;
            const int tc    = r / 9;
            const int c     = tc & 7;
            const int t     = tc >> 3;
            const float* base = (t == 0 ? Q : (t == 1 ? Kt : V))
                + (size_t)(chbase + c) * D3;
            const int hh  = h0 + (token / 3) * 4;
            const int wwp = w0 + (token % 3) * 4;
            const float* p = base + hh * D2 + wwp * D + pdl * 4;
            float mx = -1e30f;
            #pragma unroll
            for (int dh = 0; dh < 4; dh++)
                #pragma unroll
                for (int dw = 0; dw < 4; dw++) {
                    float4 a = __ldg((const float4*)(p + dh * D2 + dw * D));
                    mx = fmaxf(mx, fmaxf(fmaxf(a.x, a.y), fmaxf(a.z, a.w)));
                }
            if (t < 2) sP[(t * 9 + token) * TS + PDOFF(pdl) + c] = mx;
            else       sV[token * VTS + pdl * 8 + c] = __float2half(mx);
        }
    } else {                              // br3: sw=8 (d-half)
        for (int e = tid; e < 648; e += 256) {
            const int c    = e & 7;
            const int r    = e >> 3;
            const int pdl  = r % 3;
            const int r2   = r / 3;
            const int token = r2 % 9;
            const int t     = r2 / 9;
            const float* base = (t == 0 ? Q : (t == 1 ? Kt : V))
                + (size_t)(chbase + c) * D3;
            const int hh  = h0 + (token / 3) * 8;
            const int wwp = w0 + (token % 3) * 8;
            const float* p = base + hh * D2 + wwp * D + dhalf * 24 + pdl * 8;
            float mx = -1e30f;
            for (int dh = 0; dh < 8; dh++) {
                const float* rowb = p + dh * D2;
                #pragma unroll
                for (int dw = 0; dw < 8; dw++) {
                    float4 a  = __ldg((const float4*)(rowb + dw * D));
                    float4 bq = __ldg((const float4*)(rowb + dw * D + 4));
                    mx = fmaxf(mx, fmaxf(fmaxf(a.x, a.y), fmaxf(a.z, a.w)));
                    mx = fmaxf(mx, fmaxf(fmaxf(bq.x, bq.y), fmaxf(bq.z, bq.w)));
                }
            }
            if (t < 2) sP[(t * 9 + token) * TS + pdl * 8 + c] = mx;
            else       sV[token * VTS + pdl * 8 + c] = __float2half(mx);
        }
    }
    __syncthreads();

    // ---- attention ----
    const int NwLoc = (br == 0) ? 8 : ((br == 3) ? 1 : Nw);
    attn_core(sP, sV, sTabH, NwLoc, tid);
    __syncthreads();

    // ---- scatter / upsample ----
    if (br == 0) {
        const int dbase = dhalf * 24;
        const size_t chD3 = (size_t)chbase * D3;
        for (int e = tid; e < 432; e += 256) {
            const int c    = e & 7;
            const int r    = e >> 3;
            const int pdq  = r % 6;
            const int token = r / 6;
            const float* src = sP + token * TS + pdq * 36 + c;
            float4 v = make_float4(src[0], src[8], src[16], src[24]);
            *(float4*)(out + chD3 + (size_t)c * D3
                       + (h0 + token / 3) * D2 + (w0 + token % 3) * D
                       + dbase + 4 * pdq) = v;
        }
    } else if (br == 1) {
        upsample_staged<1, 8>(sP, sI0, sF, out, chbase, h0, w0, 0, tid);
    } else if (br == 2) {
        upsample_staged<2, 4>(sP, sI0, sF, out, chbase, h0, w0, 0, tid);
    } else {
        upsample_staged<3, 1>(sP, sI0, sF, out, chbase, h0, w0, dhalf, tid);
    }
}

extern "C" void kernel_launch(void* const* d_in, const int* in_sizes, int n_in,
                              void* d_out, int out_size)
{
    const float* Q   = (const float*)d_in[0];
    const float* K   = (const float*)d_in[1];
    const float* V   = (const float*)d_in[2];
    const float* tab = (const float*)d_in[3];
    float* out = (float*)d_out;

    fusedK<<<4800, 256>>>(Q, K, V, tab, out);
}

// round 14
// speedup vs baseline: 1.0542x; 1.0542x over previous
#include <cuda_runtime.h>
#include <math.h>

#define D  48
#define D2 (48*48)
#define D3 (48*48*48)
#define TS 216     // token-row stride: 6 quads * 36 floats (bank-padded)

// padded pd offset: quad stride 36 (not 32) -> conflict-free c-transposes
#define PDOFF(pd) ((((pd) >> 2) * 36) + (((pd) & 3) * 8))

#define STG_STRIDE 52
#define STG_ROWS   8

// log2(e) / sqrt(8)
#define EXP2_SCALE 0.51012063731f

// ---------------------------------------------------------------------------
// attention core: warp-per-window, c-innermost padded smem, windows [0,NwLoc)
// ---------------------------------------------------------------------------
__device__ __forceinline__ void attn_core(
    float* __restrict__ sP, const float* __restrict__ sTabH,
    int NwLoc, int tid)
{
    const int warp = tid >> 5, lane = tid & 31;
    const int mh = lane / 9, mw = (lane / 3) % 3, md = lane % 3;
    const int tq = mh * 3 + mw;
    const int mbase = mh * 25 + mw * 5 + md + 62;

    for (int wd = warp; wd < NwLoc; wd += 8) {
        if (lane < 27) {
            const int wd3 = wd * 3;
            const int offs[3] = { PDOFF(wd3), PDOFF(wd3 + 1), PDOFF(wd3 + 2) };
            const int offm = offs[md];

            float* qp = sP + tq * TS + offm;
            const float4 q0 = *(const float4*)qp;
            const float4 q1 = *(const float4*)(qp + 4);

            float s[27];
            #pragma unroll
            for (int n = 0; n < 27; n++) {
                const int tn = n / 3, nd = n % 3;
                const float* kp = sP + (9 + tn) * TS + offs[nd];
                const float4 k0 = *(const float4*)kp;
                const float4 k1 = *(const float4*)(kp + 4);
                s[n] = q0.x * k0.x + q0.y * k0.y + q0.z * k0.z + q0.w * k0.w
                     + q1.x * k1.x + q1.y * k1.y + q1.z * k1.z + q1.w * k1.w;
            }
            // no-max softmax via exp2 (scores bounded -> fp32-safe)
            float sum = 0.f;
            #pragma unroll
            for (int n = 0; n < 27; n++) { s[n] = exp2f(s[n] * EXP2_SCALE); sum += s[n]; }
            const float inv = 1.0f / sum;
            #pragma unroll
            for (int n = 0; n < 27; n++) {
                const int nh = n / 9, nw = (n / 3) % 3, nd = n % 3;
                s[n] = s[n] * inv + sTabH[mbase - (nh * 25 + nw * 5 + nd)];
            }
            float4 a0 = make_float4(0.f, 0.f, 0.f, 0.f);
            float4 a1 = make_float4(0.f, 0.f, 0.f, 0.f);
            #pragma unroll
            for (int n = 0; n < 27; n++) {
                const int tn = n / 3, nd = n % 3;
                const float* vp = sP + (18 + tn) * TS + offs[nd];
                const float4 v0 = *(const float4*)vp;
                const float4 v1 = *(const float4*)(vp + 4);
                const float sn = s[n];
                a0.x += sn * v0.x; a0.y += sn * v0.y;
                a0.z += sn * v0.z; a0.w += sn * v0.w;
                a1.x += sn * v1.x; a1.y += sn * v1.y;
                a1.z += sn * v1.z; a1.w += sn * v1.w;
            }
            *(float4*)qp       = a0;
            *(float4*)(qp + 4) = a1;
        }
    }
}

// ---------------------------------------------------------------------------
// upsample (br>=1): lane-quarter compute into staging carved from the dead
// k/v smem region, then coalesced float4 copy-out.
// ---------------------------------------------------------------------------
template<int BR, int NWLOC>
__device__ __forceinline__ void upsample_staged(
    float* __restrict__ sP, const int* __restrict__ sI0,
    const float* __restrict__ sF, float* __restrict__ out,
    int chbase, int h0, int w0, int dhalf, int tid)
{
    constexpr int BW   = 3 << BR;
    constexpr int LEN  = NWLOC * BW;      // d extent: 48,48,24
    constexpr int QLEN = LEN / 4;         // per-lane quarter
    constexpr int ROWS = 8 * BW * BW;
    constexpr int RPW  = ROWS / 8;        // rows per warp
    const int warp = tid >> 5, lane = tid & 31;
    float* stg = sP + 9 * TS + warp * STG_ROWS * STG_STRIDE;  // dead k/v region
    const int dbase = dhalf * LEN;
    const size_t chD3 = (size_t)chbase * D3;
    const int rw0 = warp * RPW;

    for (int rb = 0; rb < RPW; rb += STG_ROWS) {
        const int nr = (RPW - rb < STG_ROWS) ? (RPW - rb) : STG_ROWS;

        // ---- compute: lane = (row, quarter) ----
        const int lrow = lane >> 2, quarter = lane & 3;
        if (lrow < nr) {
            const int r   = rw0 + rb + lrow;
            const int c   = r / (BW * BW);
            const int rem = r - c * (BW * BW);
            const int lh  = rem / BW;
            const int lw  = rem - lh * BW;

            const int   ih0 = sI0[lh], iw0 = sI0[lw];
            const int   ih1 = (ih0 < 2) ? ih0 + 1 : 2;
            const int   iw1 = (iw0 < 2) ? iw0 + 1 : 2;
            const float fh  = sF[lh],  fw  = sF[lw];

            const int o00 = (ih0 * 3 + iw0) * TS + c;
            const int o01 = (ih0 * 3 + iw1) * TS + c;
            const int o10 = (ih1 * 3 + iw0) * TS + c;
            const int o11 = (ih1 * 3 + iw1) * TS + c;

            float* srow = stg + lrow * STG_STRIDE + quarter * QLEN;

            if (BR < 3) {
                constexpr int WPQ = QLEN / BW;        // 2 (br1), 1 (br2)
                const int wdb = quarter * WPQ;
                #pragma unroll
                for (int wi = 0; wi < WPQ; wi++) {
                    const int wd3 = (wdb + wi) * 3;
                    const int pos3[3] = { PDOFF(wd3), PDOFF(wd3 + 1), PDOFF(wd3 + 2) };
                    float T[3];
                    #pragma unroll
                    for (int id = 0; id < 3; id++) {
                        const int po = pos3[id];
                        const float t00 = sP[o00 + po], t01 = sP[o01 + po];
                        const float t10 = sP[o10 + po], t11 = sP[o11 + po];
                        const float a0 = t00 + fw * (t01 - t00);
                        const float a1 = t10 + fw * (t11 - t10);
                        T[id] = a0 + fh * (a1 - a0);
                    }
                    #pragma unroll
                    for (int ld = 0; ld < BW; ld += 2) {
                        float pr[2];
                        #pragma unroll
                        for (int j = 0; j < 2; j++) {
                            const float pos = (float)(ld + j) * (2.0f / (float)(BW - 1));
                            const int   id0 = (pos >= 2.0f) ? 2 : (int)pos;
                            const float fd  = pos - (float)id0;
                            const float lo = T[id0];
                            const float hi = T[(id0 < 2) ? id0 + 1 : 2];
                            pr[j] = lo + fd * (hi - lo);
                        }
                        *(float2*)(srow + wi * BW + ld) = make_float2(pr[0], pr[1]);
                    }
                }
            } else {                                   // BR==3: QLEN=6 of one window
                float T[3];
                #pragma unroll
                for (int id = 0; id < 3; id++) {
                    const int po = id * 8;             // PDOFF(0..2) = 0,8,16
                    const float t00 = sP[o00 + po], t01 = sP[o01 + po];
                    const float t10 = sP[o10 + po], t11 = sP[o11 + po];
                    const float a0 = t00 + fw * (t01 - t00);
                    const float a1 = t10 + fw * (t11 - t10);
                    T[id] = a0 + fh * (a1 - a0);
                }
                const int ldb = quarter * 6;
                #pragma unroll
                for (int j = 0; j < 6; j += 2) {
                    float pr[2];
                    #pragma unroll
                    for (int jj = 0; jj < 2; jj++) {
                        const float pos = (float)(ldb + j + jj) * (2.0f / 23.0f);
                        const int   id0 = (pos >= 2.0f) ? 2 : (int)pos;
                        const float fd  = pos - (float)id0;
                        const float lo = T[id0];
                        const float hi = T[(id0 < 2) ? id0 + 1 : 2];
                        pr[jj] = lo + fd * (hi - lo);
                    }
                    *(float2*)(srow + j) = make_float2(pr[0], pr[1]);
                }
            }
        }
        __syncwarp();

        // ---- copy: coalesced float4 out ----
        const int nq = nr * (LEN / 4);
        for (int i = lane; i < nq; i += 32) {
            const int row    = (i * 4) / LEN;
            const int within = (i * 4) - row * LEN;
            float4 v = *(const float4*)(stg + row * STG_STRIDE + within);
            const int r   = rw0 + rb + row;
            const int c   = r / (BW * BW);
            const int rem = r - c * (BW * BW);
            const int lh  = rem / BW;
            const int lw  = rem - lh * BW;
            *(float4*)(out + chD3 + (size_t)c * D3
                       + (h0 + lh) * D2 + (w0 + lw) * D + dbase + within) = v;
        }
        __syncwarp();
    }
}

// ---------------------------------------------------------------------------
// fusedK: pool-in-CTA + attention + upsample, all branches, one launch.
// grid 4800: [0,64) br3 d-split | [64,192) br2 | [192,704) br1 | [704,4800) br0
// ---------------------------------------------------------------------------
__global__ __launch_bounds__(256, 4) void fusedK(
    const float* __restrict__ Q, const float* __restrict__ Kt,
    const float* __restrict__ V, const float* __restrict__ tab,
    float* __restrict__ out)
{
    __shared__ float sP[27 * TS];          // 23328 B (k/v region doubles as staging)
    __shared__ float sTabH[125];
    __shared__ int   sI0[24];
    __shared__ float sF[24];

    const int cid = blockIdx.x;
    const int tid = threadIdx.x;

    int br, bh, line, dhalf;
    if (cid < 64) {
        br = 3; bh = cid >> 3;
        const int s = cid & 7;
        line = s >> 1; dhalf = s & 1;
    } else if (cid < 192) {
        br = 2; const int s = cid - 64;
        bh = s >> 4; line = s & 15; dhalf = 0;
    } else if (cid < 704) {
        br = 1; const int s = cid - 192;
        bh = s >> 6; line = s & 63; dhalf = 0;
    } else {
        br = 0; const int s = cid - 704;
        bh = s >> 9;
        const int rest = s & 511;
        line = rest >> 1; dhalf = rest & 1;
    }

    const int Nw = 16 >> br;
    const int bw = 3 << br;
    const int wh = line / Nw, ww = line - wh * Nw;
    const int b = bh >> 1, head = bh & 1;
    const int chbase = b * 64 + br * 16 + head * 8;
    const int h0 = wh * bw, w0 = ww * bw;

    if (tid < 125) sTabH[tid] = __ldg(tab + tid * 2 + head);
    if (tid >= 128 && tid - 128 < bw) {
        const int u = tid - 128;
        const float pos = (float)u * (2.0f / (float)(bw - 1));
        int i0 = (int)pos;
        if (i0 > 2) i0 = 2;
        sI0[u] = i0;
        sF[u]  = pos - (float)i0;
    }

    // ---- pool raw input directly into padded c-innermost smem ----
    if (br == 0) {
        const int dbase = dhalf * 24;
        for (int e = tid; e < 1296; e += 256) {           // 3t*9tok*6q*8c
            const int c    = e & 7;
            const int r    = e >> 3;
            const int pdq  = r % 6;
            const int r2   = r / 6;
            const int token = r2 % 9;
            const int t     = r2 / 9;
            const float* base = (t == 0 ? Q : (t == 1 ? Kt : V))
                + (size_t)(chbase + c) * D3
                + (h0 + token / 3) * D2 + (w0 + token % 3) * D + dbase + 4 * pdq;
            float4 v = __ldg((const float4*)base);
            float* dst = sP + (t * 9 + token) * TS + pdq * 36 + c;
            dst[0] = v.x; dst[8] = v.y; dst[16] = v.z; dst[24] = v.w;
        }
    } else if (br == 1) {                 // sw=2, pdl-innermost lanes (coalesced)
        for (int e = tid; e < 5184; e += 256) {
            const int pdl  = e % 24;
            const int r    = e / 24;
            const int token = r % 9;
            const int tc    = r / 9;
            const int c     = tc & 7;
            const int t     = tc >> 3;
            const float* base = (t == 0 ? Q : (t == 1 ? Kt : V))
                + (size_t)(chbase + c) * D3;
            const int hh  = h0 + (token / 3) * 2;
            const int wwp = w0 + (token % 3) * 2;
            const float* p = base + hh * D2 + wwp * D + pdl * 2;
            float mx = -1e30f;
            #pragma unroll
            for (int dh = 0; dh < 2; dh++)
                #pragma unroll
                for (int dw = 0; dw < 2; dw++) {
                    float2 a = __ldg((const float2*)(p + dh * D2 + dw * D));
                    mx = fmaxf(mx, fmaxf(a.x, a.y));
                }
            sP[(t * 9 + token) * TS + PDOFF(pdl) + c] = mx;
        }
    } else if (br == 2) {                 // sw=4, pdl-innermost lanes (coalesced)
        for (int e = tid; e < 2592; e += 256) {
            const int pdl  = e % 12;
            const int r    = e / 12;
            const int token = r % 9;
            const int tc    = r / 9;
            const int c     = tc & 7;
            const int t     = tc >> 3;
            const float* base = (t == 0 ? Q : (t == 1 ? Kt : V))
                + (size_t)(chbase + c) * D3;
            const int hh  = h0 + (token / 3) * 4;
            const int wwp = w0 + (token % 3) * 4;
            const float* p = base + hh * D2 + wwp * D + pdl * 4;
            float mx = -1e30f;
            #pragma unroll
            for (int dh = 0; dh < 4; dh++)
                #pragma unroll
                for (int dw = 0; dw < 4; dw++) {
                    float4 a = __ldg((const float4*)(p + dh * D2 + dw * D));
                    mx = fmaxf(mx, fmaxf(fmaxf(a.x, a.y), fmaxf(a.z, a.w)));
                }
            sP[(t * 9 + token) * TS + PDOFF(pdl) + c] = mx;
        }
    } else {                              // br3: sw=8 (d-half)
        for (int e = tid; e < 648; e += 256) {
            const int c    = e & 7;
            const int r    = e >> 3;
            const int pdl  = r % 3;
            const int r2   = r / 3;
            const int token = r2 % 9;
            const int t     = r2 / 9;
            const float* base = (t == 0 ? Q : (t == 1 ? Kt : V))
                + (size_t)(chbase + c) * D3;
            const int hh  = h0 + (token / 3) * 8;
            const int wwp = w0 + (token % 3) * 8;
            const float* p = base + hh * D2 + wwp * D + dhalf * 24 + pdl * 8;
            float mx = -1e30f;
            for (int dh = 0; dh < 8; dh++) {
                const float* rowb = p + dh * D2;
                #pragma unroll
                for (int dw = 0; dw < 8; dw++) {
                    float4 a  = __ldg((const float4*)(rowb + dw * D));
                    float4 bq = __ldg((const float4*)(rowb + dw * D + 4));
                    mx = fmaxf(mx, fmaxf(fmaxf(a.x, a.y), fmaxf(a.z, a.w)));
                    mx = fmaxf(mx, fmaxf(fmaxf(bq.x, bq.y), fmaxf(bq.z, bq.w)));
                }
            }
            sP[(t * 9 + token) * TS + pdl * 8 + c] = mx;
        }
    }
    __syncthreads();

    // ---- attention ----
    const int NwLoc = (br == 0) ? 8 : ((br == 3) ? 1 : Nw);
    attn_core(sP, sTabH, NwLoc, tid);
    __syncthreads();

    // ---- scatter / upsample ----
    if (br == 0) {
        const int dbase = dhalf * 24;
        const size_t chD3 = (size_t)chbase * D3;
        for (int e = tid; e < 432; e += 256) {
            const int c    = e & 7;
            const int r    = e >> 3;
            const int pdq  = r % 6;
            const int token = r / 6;
            const float* src = sP + token * TS + pdq * 36 + c;
            float4 v = make_float4(src[0], src[8], src[16], src[24]);
            *(float4*)(out + chD3 + (size_t)c * D3
                       + (h0 + token / 3) * D2 + (w0 + token % 3) * D
                       + dbase + 4 * pdq) = v;
        }
    } else if (br == 1) {
        upsample_staged<1, 8>(sP, sI0, sF, out, chbase, h0, w0, 0, tid);
    } else if (br == 2) {
        upsample_staged<2, 4>(sP, sI0, sF, out, chbase, h0, w0, 0, tid);
    } else {
        upsample_staged<3, 1>(sP, sI0, sF, out, chbase, h0, w0, dhalf, tid);
    }
}

extern "C" void kernel_launch(void* const* d_in, const int* in_sizes, int n_in,
                              void* d_out, int out_size)
{
    const float* Q   = (const float*)d_in[0];
    const float* K   = (const float*)d_in[1];
    const float* V   = (const float*)d_in[2];
    const float* tab = (const float*)d_in[3];
    float* out = (float*)d_out;

    fusedK<<<4800, 256>>>(Q, K, V, tab, out);
}